// round 13
// baseline (speedup 1.0000x reference)
#include <cuda_runtime.h>
#include <cuda_bf16.h>

// ---------------- geometry ----------------
#define L0      512
#define P1_O    254
#define N1      (P1_O*P1_O)  // 64516
#define P3_O    125
#define NP3     (16*125*125) // 250000
#define N4P3    (NP3/4)      // 62500 float4
#define F6OUT   98304
#define NOUT    54
#define C5_NS   25           // 62500/25 = 2500 exact
#define FIN_NS  12           // 24576/12 = 2048 exact

// ---------------- scratch ----------------
__device__ __align__(16) float g_p1[6*N1];
__device__ __align__(16) float g_p3[NP3];
__device__ __align__(16) float g_c5part[120*C5_NS];
__device__ __align__(16) float g_c5[120];
__device__ __align__(16) float g_f6[F6OUT];
__device__ __align__(16) float g_fpart[NOUT*FIN_NS];
__device__ int g_c5cnt;
__device__ int g_fincnt;

__device__ __forceinline__ float dot4(float4 a, float4 b) {
    return a.x*b.x + a.y*b.y + a.z*b.z + a.w*b.w;
}

// ---------------- C1 conv+pool: one thread per (pooled px, out channel) ----------------
__global__ void k_c1p1(const float* __restrict__ x,
                       const float* __restrict__ W1,
                       const float* __restrict__ b1) {
    cudaTriggerProgrammaticLaunchCompletion();
    __shared__ float sw[150];
    __shared__ float sb[6];
    if (threadIdx.x < 150) sw[threadIdx.x] = W1[threadIdx.x];
    if (threadIdx.x < 6)   sb[threadIdx.x] = b1[threadIdx.x];
    __syncthreads();

    int idx = blockIdx.x * blockDim.x + threadIdx.x;
    if (idx >= 6 * N1) return;
    int oc  = idx / N1;
    int px0 = idx % N1;
    int py = px0 / P1_O, px = px0 % P1_O;

    float p[36];
#pragma unroll
    for (int i = 0; i < 6; i++)
#pragma unroll
        for (int j = 0; j < 6; j++)
            p[i*6+j] = x[(2*py + i)*L0 + 2*px + j];

    float b = sb[oc];
    float a00 = b, a01 = b, a10 = b, a11 = b;
    const float* w = &sw[oc*25];
#pragma unroll
    for (int i = 0; i < 5; i++)
#pragma unroll
        for (int j = 0; j < 5; j++) {
            float wv = w[i*5 + j];
            a00 = fmaf(p[ i   *6 + j    ], wv, a00);
            a01 = fmaf(p[ i   *6 + j + 1], wv, a01);
            a10 = fmaf(p[(i+1)*6 + j    ], wv, a10);
            a11 = fmaf(p[(i+1)*6 + j + 1], wv, a11);
        }
    g_p1[oc*N1 + px0] = 0.25f * (fmaxf(a00,0.f) + fmaxf(a01,0.f) +
                                 fmaxf(a10,0.f) + fmaxf(a11,0.f));
}

// ---------------- C3 sparse conv+pool (PDL secondary) ----------------
__global__ void k_c3p3(const float* __restrict__ W3,
                       const float* __restrict__ b3) {
    cudaTriggerProgrammaticLaunchCompletion();
    int oc = blockIdx.y;
    __shared__ float sw[150];
    __shared__ float sb;
    if (threadIdx.x < 150) sw[threadIdx.x] = W3[oc*150 + threadIdx.x];
    if (threadIdx.x == 0)  sb = b3[oc];
    cudaGridDependencySynchronize();     // wait for c1p1 grid completion
    __syncthreads();

    const unsigned MASKS[16] = {
        0x07u, 0x0Eu, 0x1Cu, 0x38u, 0x31u, 0x23u,
        0x0Fu, 0x1Eu, 0x3Cu, 0x39u, 0x33u, 0x27u,
        0x1Bu, 0x36u, 0x2Du, 0x3Fu };
    unsigned mask = MASKS[oc];

    int idx = blockIdx.x * blockDim.x + threadIdx.x;
    if (idx >= P3_O * P3_O) return;
    int py = idx / P3_O, px = idx % P3_O;

    float b = sb;
    float a00 = b, a01 = b, a10 = b, a11 = b;

#pragma unroll
    for (int c = 0; c < 6; c++) {
        if ((mask >> c) & 1u) {
            float p[36];
            const float* src = g_p1 + c*N1 + (2*py)*P1_O + 2*px;
#pragma unroll
            for (int i = 0; i < 6; i++)
#pragma unroll
                for (int j = 0; j < 6; j++)
                    p[i*6+j] = src[i*P1_O + j];
#pragma unroll
            for (int i = 0; i < 5; i++)
#pragma unroll
                for (int j = 0; j < 5; j++) {
                    float w = sw[c*25 + i*5 + j];
                    a00 = fmaf(p[ i   *6 + j    ], w, a00);
                    a01 = fmaf(p[ i   *6 + j + 1], w, a01);
                    a10 = fmaf(p[(i+1)*6 + j    ], w, a10);
                    a11 = fmaf(p[(i+1)*6 + j + 1], w, a11);
                }
        }
    }
    g_p3[oc*P3_O*P3_O + idx] = 0.25f * (fmaxf(a00,0.f) + fmaxf(a01,0.f) +
                                        fmaxf(a10,0.f) + fmaxf(a11,0.f));
}

// ---------------- C5: 8 outputs/block, split-K (PDL secondary) ----------------
__global__ void __launch_bounds__(256, 3) k_c5(const float* __restrict__ W5,
                                               const float* __restrict__ b5) {
    cudaTriggerProgrammaticLaunchCompletion();
    int og = blockIdx.x;          // 0..14
    int s  = blockIdx.y;          // 0..C5_NS-1
    const int per = N4P3 / C5_NS; // 2500
    int start = s * per, end = start + per;

    const float4* __restrict__ h = (const float4*)g_p3;
    const float4* w[8];
#pragma unroll
    for (int r = 0; r < 8; r++)
        w[r] = (const float4*)(W5 + (size_t)(8*og + r) * NP3);

    cudaGridDependencySynchronize();     // wait for c3p3 grid completion

    float acc[8];
#pragma unroll
    for (int r = 0; r < 8; r++) acc[r] = 0.f;

#pragma unroll 2
    for (int i = start + threadIdx.x; i < end; i += 256) {
        float4 hv = h[i];
        float4 xv[8];
#pragma unroll
        for (int r = 0; r < 8; r++) xv[r] = __ldcs(&w[r][i]);
#pragma unroll
        for (int r = 0; r < 8; r++) acc[r] += dot4(xv[r], hv);
    }

    __shared__ float red[8*256];
#pragma unroll
    for (int r = 0; r < 8; r++) red[r*256 + threadIdx.x] = acc[r];
    __syncthreads();
    {
        int r = threadIdx.x >> 5;
        int c = threadIdx.x & 31;
        float v = 0.f;
#pragma unroll
        for (int k = 0; k < 8; k++) v += red[r*256 + c + 32*k];
#pragma unroll
        for (int off = 16; off > 0; off >>= 1)
            v += __shfl_down_sync(0xFFFFFFFFu, v, off);
        if (c == 0) g_c5part[(8*og + r) * C5_NS + s] = v;
    }

    __shared__ int slast;
    __syncthreads();
    if (threadIdx.x == 0) {
        __threadfence();
        int t = atomicAdd(&g_c5cnt, 1);
        slast = (t == 15*C5_NS - 1);
    }
    __syncthreads();
    if (slast) {
        int oo = threadIdx.x;
        if (oo < 120) {
            float a = b5[oo];
#pragma unroll
            for (int ss = 0; ss < C5_NS; ss++) a += g_c5part[oo*C5_NS + ss];
            g_c5[oo] = fmaxf(a, 0.0f);
        }
        if (threadIdx.x == 0) g_c5cnt = 0;
    }
}

// ---------------- F6: GEMV 98304x120 (round-5 body; PDL secondary) ----------------
__global__ void k_f6(const float* __restrict__ W6,
                     const float* __restrict__ b6) {
    cudaTriggerProgrammaticLaunchCompletion();
    __shared__ __align__(16) float sc[120];
    cudaGridDependencySynchronize();     // wait for c5 grid completion
    if (threadIdx.x < 120) sc[threadIdx.x] = g_c5[threadIdx.x];
    __syncthreads();

    int warp = threadIdx.x >> 5;
    int lane = threadIdx.x & 31;
    int quad = lane & 3;
    int row  = (blockIdx.x * 8 + warp) * 8 + (lane >> 2);

    const float4* __restrict__ w  = (const float4*)(W6 + (size_t)row * 120);
    const float4* __restrict__ s4 = (const float4*)sc;

    float acc0 = 0.0f, acc1 = 0.0f;
#pragma unroll
    for (int it = 0; it < 8; it++) {
        int k = quad + it * 4;
        if (k < 30) {
            float4 a = __ldg(&w[k]);
            float4 b = s4[k];
            float d = dot4(a, b);
            if (it & 1) acc1 += d; else acc0 += d;
        }
    }
    float acc = acc0 + acc1;
    acc += __shfl_xor_sync(0xFFFFFFFFu, acc, 1);
    acc += __shfl_xor_sync(0xFFFFFFFFu, acc, 2);
    if (quad == 0)
        g_f6[row] = fmaxf(acc + __ldg(&b6[row]), 0.0f);
}

// ---------------- final: GEMV 54x98304 (PDL secondary, W7 preload) ----------------
__global__ void __launch_bounds__(256, 4) k_fin(const float* __restrict__ W7,
                                                const float* __restrict__ b7,
                                                float* __restrict__ out) {
    int o = blockIdx.x;
    int s = blockIdx.y;
    const float4* __restrict__ w = (const float4*)(W7 + (size_t)o * F6OUT);
    const float4* __restrict__ h = (const float4*)g_f6;
    const int per = (F6OUT/4) / FIN_NS;    // 2048
    int base = s * per + threadIdx.x;

    // independent prologue: first 4 W7 loads in flight before the dependency
    float4 wv[4];
#pragma unroll
    for (int it = 0; it < 4; it++) wv[it] = __ldcs(&w[base + it * 256]);

    cudaGridDependencySynchronize();     // wait for f6 grid completion

    float acc0 = 0.f, acc1 = 0.f;
#pragma unroll
    for (int it = 0; it < 4; it++) {
        float4 b = h[base + it * 256];
        float d = dot4(wv[it], b);
        if (it & 1) acc1 += d; else acc0 += d;
    }
#pragma unroll
    for (int it = 4; it < 8; it++) {
        int i = base + it * 256;
        float4 a = __ldcs(&w[i]);
        float4 b = h[i];
        float d = dot4(a, b);
        if (it & 1) acc1 += d; else acc0 += d;
    }
    float acc = acc0 + acc1;

    __shared__ float red[256];
    red[threadIdx.x] = acc;
    __syncthreads();
#pragma unroll
    for (int st = 128; st > 0; st >>= 1) {
        if (threadIdx.x < st) red[threadIdx.x] += red[threadIdx.x + st];
        __syncthreads();
    }
    __shared__ int slast;
    if (threadIdx.x == 0) {
        g_fpart[o * FIN_NS + s] = red[0];
        __threadfence();
        int t = atomicAdd(&g_fincnt, 1);
        slast = (t == NOUT*FIN_NS - 1);
    }
    __syncthreads();
    if (slast) {
        int oo = threadIdx.x;
        if (oo < NOUT) {
            float a = b7[oo];
#pragma unroll
            for (int ss = 0; ss < FIN_NS; ss++) a += g_fpart[oo*FIN_NS + ss];
            out[oo] = a;
        }
        if (threadIdx.x == 0) g_fincnt = 0;
    }
}

// ---------------- launch (PDL-chained) ----------------
template <typename K, typename... Args>
static void launch_pdl(K kern, dim3 grid, dim3 block, bool pdl, Args... args) {
    cudaLaunchConfig_t cfg = {};
    cfg.gridDim = grid;
    cfg.blockDim = block;
    cudaLaunchAttribute attr[1];
    if (pdl) {
        attr[0].id = cudaLaunchAttributeProgrammaticStreamSerialization;
        attr[0].val.programmaticStreamSerializationAllowed = 1;
        cfg.attrs = attr;
        cfg.numAttrs = 1;
    }
    cudaLaunchKernelEx(&cfg, kern, args...);
}

extern "C" void kernel_launch(void* const* d_in, const int* in_sizes, int n_in,
                              void* d_out, int out_size) {
    const float* x  = (const float*)d_in[0];
    const float* W1 = (const float*)d_in[1];
    const float* b1 = (const float*)d_in[2];
    const float* W3 = (const float*)d_in[3];
    const float* b3 = (const float*)d_in[4];
    const float* W5 = (const float*)d_in[5];
    const float* b5 = (const float*)d_in[6];
    const float* W6 = (const float*)d_in[7];
    const float* b6 = (const float*)d_in[8];
    const float* W7 = (const float*)d_in[9];
    const float* b7 = (const float*)d_in[10];
    float* out = (float*)d_out;

    launch_pdl(k_c1p1, dim3((6*N1 + 255)/256), dim3(256), false, x, W1, b1);
    launch_pdl(k_c3p3, dim3((P3_O*P3_O + 255)/256, 16), dim3(256), true, W3, b3);
    launch_pdl(k_c5,   dim3(15, C5_NS), dim3(256), true, W5, b5);
    launch_pdl(k_f6,   dim3(F6OUT/64), dim3(256), true, W6, b6);
    launch_pdl(k_fin,  dim3(NOUT, FIN_NS), dim3(256), true, W7, b7, out);
}

// round 14
// speedup vs baseline: 1.0489x; 1.0489x over previous
#include <cuda_runtime.h>
#include <cuda_bf16.h>

// ---------------- geometry ----------------
#define L0      512
#define P1_O    254
#define P3_O    125
#define NP3     (16*125*125) // 250000
#define N4P3    (NP3/4)      // 62500 float4
#define F6OUT   98304
#define NOUT    54
#define C5_NS   25           // 62500/25 = 2500 exact
#define FIN_NS  12           // 24576/12 = 2048 exact
#define F6_BLKS 768          // 128 rows per block (16 per warp)

// ---------------- scratch ----------------
__device__ __align__(16) float g_p1[6*P1_O*P1_O];
__device__ __align__(16) float g_p3[NP3];
__device__ __align__(16) float g_c5part[120*C5_NS];
__device__ __align__(16) float g_c5[120];
__device__ __align__(16) float g_f6[F6OUT];
__device__ __align__(16) float g_fpart[NOUT*FIN_NS];
__device__ int g_c5cnt;
__device__ int g_fincnt;

__device__ __forceinline__ float dot4(float4 a, float4 b) {
    return a.x*b.x + a.y*b.y + a.z*b.z + a.w*b.w;
}

// ---------------- fused C1 conv 5x5 + ReLU + 2x2 avgpool ----------------
__global__ void k_c1p1(const float* __restrict__ x,
                       const float* __restrict__ W1,
                       const float* __restrict__ b1) {
    __shared__ float sw[6*25];
    __shared__ float sb[6];
    if (threadIdx.x < 150) sw[threadIdx.x] = W1[threadIdx.x];
    if (threadIdx.x < 6)   sb[threadIdx.x] = b1[threadIdx.x];
    __syncthreads();

    int idx = blockIdx.x * blockDim.x + threadIdx.x;
    if (idx >= P1_O * P1_O) return;
    int py = idx / P1_O, px = idx % P1_O;

    float p[36];
#pragma unroll
    for (int i = 0; i < 6; i++)
#pragma unroll
        for (int j = 0; j < 6; j++)
            p[i*6+j] = x[(2*py + i)*L0 + 2*px + j];

#pragma unroll
    for (int o = 0; o < 6; o++) {
        float b = sb[o];
        float a00 = b, a01 = b, a10 = b, a11 = b;
#pragma unroll
        for (int i = 0; i < 5; i++)
#pragma unroll
            for (int j = 0; j < 5; j++) {
                float w = sw[o*25 + i*5 + j];
                a00 = fmaf(p[ i   *6 + j    ], w, a00);
                a01 = fmaf(p[ i   *6 + j + 1], w, a01);
                a10 = fmaf(p[(i+1)*6 + j    ], w, a10);
                a11 = fmaf(p[(i+1)*6 + j + 1], w, a11);
            }
        g_p1[o*P1_O*P1_O + idx] = 0.25f * (fmaxf(a00,0.f) + fmaxf(a01,0.f) +
                                           fmaxf(a10,0.f) + fmaxf(a11,0.f));
    }
}

// ---------------- fused C3 sparse conv 5x5 + ReLU + 2x2 avgpool ----------------
__global__ void k_c3p3(const float* __restrict__ W3,
                       const float* __restrict__ b3) {
    int oc = blockIdx.y;
    __shared__ float sw[6*25];
    __shared__ float sb;
    if (threadIdx.x < 150) sw[threadIdx.x] = W3[oc*150 + threadIdx.x];
    if (threadIdx.x == 0)  sb = b3[oc];
    __syncthreads();

    const unsigned MASKS[16] = {
        0x07u, 0x0Eu, 0x1Cu, 0x38u, 0x31u, 0x23u,
        0x0Fu, 0x1Eu, 0x3Cu, 0x39u, 0x33u, 0x27u,
        0x1Bu, 0x36u, 0x2Du, 0x3Fu };
    unsigned mask = MASKS[oc];

    int idx = blockIdx.x * blockDim.x + threadIdx.x;
    if (idx >= P3_O * P3_O) return;
    int py = idx / P3_O, px = idx % P3_O;

    float b = sb;
    float a00 = b, a01 = b, a10 = b, a11 = b;

#pragma unroll
    for (int c = 0; c < 6; c++) {
        if ((mask >> c) & 1u) {
            float p[36];
            const float* src = g_p1 + c*P1_O*P1_O + (2*py)*P1_O + 2*px;
#pragma unroll
            for (int i = 0; i < 6; i++)
#pragma unroll
                for (int j = 0; j < 6; j++)
                    p[i*6+j] = src[i*P1_O + j];
#pragma unroll
            for (int i = 0; i < 5; i++)
#pragma unroll
                for (int j = 0; j < 5; j++) {
                    float w = sw[c*25 + i*5 + j];
                    a00 = fmaf(p[ i   *6 + j    ], w, a00);
                    a01 = fmaf(p[ i   *6 + j + 1], w, a01);
                    a10 = fmaf(p[(i+1)*6 + j    ], w, a10);
                    a11 = fmaf(p[(i+1)*6 + j + 1], w, a11);
                }
        }
    }
    g_p3[oc*P3_O*P3_O + idx] = 0.25f * (fmaxf(a00,0.f) + fmaxf(a01,0.f) +
                                        fmaxf(a10,0.f) + fmaxf(a11,0.f));
}

// ---------------- C5: 8 outputs/block, split-K, last-block reduce ----------------
__global__ void __launch_bounds__(256, 3) k_c5(const float* __restrict__ W5,
                                               const float* __restrict__ b5) {
    int og = blockIdx.x;          // 0..14
    int s  = blockIdx.y;          // 0..C5_NS-1
    const int per = N4P3 / C5_NS; // 2500
    int start = s * per, end = start + per;

    const float4* __restrict__ h = (const float4*)g_p3;
    const float4* w[8];
#pragma unroll
    for (int r = 0; r < 8; r++)
        w[r] = (const float4*)(W5 + (size_t)(8*og + r) * NP3);

    float acc[8];
#pragma unroll
    for (int r = 0; r < 8; r++) acc[r] = 0.f;

#pragma unroll 4
    for (int i = start + threadIdx.x; i < end; i += 256) {
        float4 hv = h[i];
        float4 xv[8];
#pragma unroll
        for (int r = 0; r < 8; r++) xv[r] = __ldcs(&w[r][i]);
#pragma unroll
        for (int r = 0; r < 8; r++) acc[r] += dot4(xv[r], hv);
    }

    __shared__ float red[8*256];
#pragma unroll
    for (int r = 0; r < 8; r++) red[r*256 + threadIdx.x] = acc[r];
    __syncthreads();
    {
        int r = threadIdx.x >> 5;
        int c = threadIdx.x & 31;
        float v = 0.f;
#pragma unroll
        for (int k = 0; k < 8; k++) v += red[r*256 + c + 32*k];
#pragma unroll
        for (int off = 16; off > 0; off >>= 1)
            v += __shfl_down_sync(0xFFFFFFFFu, v, off);
        if (c == 0) g_c5part[(8*og + r) * C5_NS + s] = v;
    }

    __shared__ int slast;
    __syncthreads();
    if (threadIdx.x == 0) {
        __threadfence();
        int t = atomicAdd(&g_c5cnt, 1);
        slast = (t == 15*C5_NS - 1);
    }
    __syncthreads();
    if (slast) {
        int oo = threadIdx.x;
        if (oo < 120) {
            float a = b5[oo];
#pragma unroll
            for (int ss = 0; ss < C5_NS; ss++) a += g_c5part[oo*C5_NS + ss];
            g_c5[oo] = fmaxf(a, 0.0f);
        }
        if (threadIdx.x == 0) g_c5cnt = 0;
    }
}

// ---------------- F6: GEMV 98304x120, 16 rows/warp interleaved ----------------
// lane = (r = lane>>2, quad = lane&3); thread carries rows r and r+8 of its
// warp's 16-row group; the 2x8 predicated loads issue back-to-back (MLP ~15).
__global__ void __launch_bounds__(256, 5) k_f6(const float* __restrict__ W6,
                                               const float* __restrict__ b6) {
    __shared__ __align__(16) float sc[120];
    if (threadIdx.x < 120) sc[threadIdx.x] = g_c5[threadIdx.x];
    __syncthreads();

    int warp = threadIdx.x >> 5;
    int lane = threadIdx.x & 31;
    int quad = lane & 3;
    int row0 = (blockIdx.x * 8 + warp) * 16 + (lane >> 2);   // rows row0, row0+8

    const float4* __restrict__ w0 = (const float4*)(W6 + (size_t)row0 * 120);
    const float4* __restrict__ w1 = (const float4*)(W6 + (size_t)(row0 + 8) * 120);
    const float4* __restrict__ s4 = (const float4*)sc;

    float accA0 = 0.f, accA1 = 0.f, accB0 = 0.f, accB1 = 0.f;
#pragma unroll
    for (int it = 0; it < 8; it++) {
        int k = quad + it * 4;
        if (k < 30) {
            float4 a0 = __ldg(&w0[k]);
            float4 a1 = __ldg(&w1[k]);
            float4 b  = s4[k];
            float d0 = dot4(a0, b);
            float d1 = dot4(a1, b);
            if (it & 1) { accA1 += d0; accB1 += d1; }
            else        { accA0 += d0; accB0 += d1; }
        }
    }
    float accA = accA0 + accA1;
    float accB = accB0 + accB1;
    accA += __shfl_xor_sync(0xFFFFFFFFu, accA, 1);
    accA += __shfl_xor_sync(0xFFFFFFFFu, accA, 2);
    accB += __shfl_xor_sync(0xFFFFFFFFu, accB, 1);
    accB += __shfl_xor_sync(0xFFFFFFFFu, accB, 2);
    if (quad == 0) {
        g_f6[row0]     = fmaxf(accA + __ldg(&b6[row0]),     0.0f);
        g_f6[row0 + 8] = fmaxf(accB + __ldg(&b6[row0 + 8]), 0.0f);
    }
}

// ---------------- final: GEMV 54x98304, split-K, last-block reduce ----------------
__global__ void __launch_bounds__(256, 4) k_fin(const float* __restrict__ W7,
                                                const float* __restrict__ b7,
                                                float* __restrict__ out) {
    int o = blockIdx.x;
    int s = blockIdx.y;
    const float4* __restrict__ w = (const float4*)(W7 + (size_t)o * F6OUT);
    const float4* __restrict__ h = (const float4*)g_f6;
    const int per = (F6OUT/4) / FIN_NS;    // 2048
    int base = s * per + threadIdx.x;

    float acc0 = 0.f, acc1 = 0.f;
#pragma unroll
    for (int it = 0; it < 8; it++) {
        int i = base + it * 256;
        float4 a = __ldcs(&w[i]);
        float4 b = h[i];
        float d = dot4(a, b);
        if (it & 1) acc1 += d; else acc0 += d;
    }
    float acc = acc0 + acc1;

    __shared__ float red[256];
    red[threadIdx.x] = acc;
    __syncthreads();
#pragma unroll
    for (int st = 128; st > 0; st >>= 1) {
        if (threadIdx.x < st) red[threadIdx.x] += red[threadIdx.x + st];
        __syncthreads();
    }
    __shared__ int slast;
    if (threadIdx.x == 0) {
        g_fpart[o * FIN_NS + s] = red[0];
        __threadfence();
        int t = atomicAdd(&g_fincnt, 1);
        slast = (t == NOUT*FIN_NS - 1);
    }
    __syncthreads();
    if (slast) {
        int oo = threadIdx.x;
        if (oo < NOUT) {
            float a = b7[oo];
#pragma unroll
            for (int ss = 0; ss < FIN_NS; ss++) a += g_fpart[oo*FIN_NS + ss];
            out[oo] = a;
        }
        if (threadIdx.x == 0) g_fincnt = 0;
    }
}

// ---------------- launch ----------------
extern "C" void kernel_launch(void* const* d_in, const int* in_sizes, int n_in,
                              void* d_out, int out_size) {
    const float* x  = (const float*)d_in[0];
    const float* W1 = (const float*)d_in[1];
    const float* b1 = (const float*)d_in[2];
    const float* W3 = (const float*)d_in[3];
    const float* b3 = (const float*)d_in[4];
    const float* W5 = (const float*)d_in[5];
    const float* b5 = (const float*)d_in[6];
    const float* W6 = (const float*)d_in[7];
    const float* b6 = (const float*)d_in[8];
    const float* W7 = (const float*)d_in[9];
    const float* b7 = (const float*)d_in[10];
    float* out = (float*)d_out;

    k_c1p1<<<(P1_O*P1_O + 255)/256, 256>>>(x, W1, b1);
    k_c3p3<<<dim3((P3_O*P3_O + 255)/256, 16), 256>>>(W3, b3);
    k_c5<<<dim3(15, C5_NS), 256>>>(W5, b5);
    k_f6<<<F6_BLKS, 256>>>(W6, b6);
    k_fin<<<dim3(NOUT, FIN_NS), 256>>>(W7, b7, out);
}